// round 14
// baseline (speedup 1.0000x reference)
#include <cuda_runtime.h>
#include <math.h>

#define D 512
#define ROWS_PER_BLOCK 8
#define THREADS 256            // 8 warps, 1 row per warp, 16 elems/lane
#define RATE 0.1f
#define CLIP_MAG 8.0f
#define EPS 1e-4f
#define ACOSH_MIN 1.0001f

__global__ __launch_bounds__(THREADS, 8)
void dropout_hyperbolic_kernel(const float* __restrict__ vecs,
                               const float* __restrict__ curvature,
                               const float* __restrict__ mask_u,
                               float* __restrict__ out)
{
    const int warp = threadIdx.x >> 5;
    const int lane = threadIdx.x & 31;
    const int row  = blockIdx.x * ROWS_PER_BLOCK + warp;

    const float4* vp = reinterpret_cast<const float4*>(vecs  + row * D);
    const float4* mp = reinterpret_cast<const float4*>(mask_u + row * D);
    float4*       op = reinterpret_cast<float4*>(out + row * D);

    // Front-batched, fully-coalesced loads: chunk i covers elements
    // [i*128 + lane*4, +4). 8 LDG.128 in flight per thread.
    // NOTE (validated R9): the scalar curvature load must stay AFTER these —
    // issuing a same-line scalar load first pollutes the L1tex queue.
    float4 v[4], m[4];
    #pragma unroll
    for (int i = 0; i < 4; i++) v[i] = vp[lane + i * 32];
    #pragma unroll
    for (int i = 0; i < 4; i++) m[i] = mp[lane + i * 32];

    // Row element 0 (lane 0, chunk 0, .x) is the hyperboloid coordinate:
    // excluded from both sums; its output is overwritten below anyway.
    if (lane == 0) v[0].x = 0.0f;

    // Pack keep decisions into a 16-bit mask (bit 4*i+j for chunk i comp j)
    // and accumulate s = sum v^2, sk = sum v^2*keep in the same pass.
    unsigned bits = 0u;
    float s_loc = 0.0f, sk_loc = 0.0f;
    #pragma unroll
    for (int i = 0; i < 4; i++) {
        bool b0 = (m[i].x >= RATE);
        bool b1 = (m[i].y >= RATE);
        bool b2 = (m[i].z >= RATE);
        bool b3 = (m[i].w >= RATE);
        bits |= (unsigned(b0) << (4*i)) | (unsigned(b1) << (4*i+1))
              | (unsigned(b2) << (4*i+2)) | (unsigned(b3) << (4*i+3));
        float x0 = v[i].x * v[i].x;
        float x1 = v[i].y * v[i].y;
        float x2 = v[i].z * v[i].z;
        float x3 = v[i].w * v[i].w;
        s_loc += x0 + x1 + x2 + x3;
        sk_loc += (b0 ? x0 : 0.0f) + (b1 ? x1 : 0.0f)
                + (b2 ? x2 : 0.0f) + (b3 ? x3 : 0.0f);
    }

    // Butterfly reduce — all lanes end with the row totals. No barriers.
    // (redux.sync.add.f32 does not exist on sm_103 — R11.)
    #pragma unroll
    for (int off = 16; off > 0; off >>= 1) {
        s_loc  += __shfl_xor_sync(0xFFFFFFFFu, s_loc,  off);
        sk_loc += __shfl_xor_sync(0xFFFFFFFFu, sk_loc, off);
    }

    // Per-row scalar tail, computed redundantly by all 32 lanes (warp-wide
    // issue: same cost as 1 lane, no broadcast needed).
    const float c = __ldg(curvature);
    const float sqrt_c = sqrtf(c);
    const float inv_keep = 1.0f / (1.0f - RATE);

    float arg = sqrtf(c + s_loc) / sqrt_c - EPS;
    arg = fmaxf(arg, ACOSH_MIN);
    // acosh(x) = log(x + sqrt(x^2 - 1)); arg >= 1.0001 so stable.
    float dist = sqrt_c * __logf(arg + sqrtf(fmaf(arg, arg, -1.0f)));
    float scale1 = dist / (sqrtf(s_loc) + EPS);

    float t = scale1 * scale1 * sk_loc * (inv_keep * inv_keep);
    float snv = sqrtf(t) / sqrt_c + EPS;
    float snv_c = fminf(fmaxf(snv, -CLIP_MAG), CLIP_MAG);

    float e  = __expf(snv_c);
    float ei = 1.0f / e;
    float cosh_v = 0.5f * (e + ei);
    float sinh_v = 0.5f * (e - ei);

    const float oscale    = (sinh_v / snv) * scale1 * inv_keep;
    const float first_val = cosh_v * sqrt_c;

    // Output pass: reconstruct dropped values from the bitmask.
    // Streaming stores (evict-first): the output is never read, so keep it
    // from evicting the L2-resident inputs between graph replays.
    #pragma unroll
    for (int i = 0; i < 4; i++) {
        float4 r;
        r.x = (bits & (1u << (4*i)))   ? oscale * v[i].x : 0.0f;
        r.y = (bits & (1u << (4*i+1))) ? oscale * v[i].y : 0.0f;
        r.z = (bits & (1u << (4*i+2))) ? oscale * v[i].z : 0.0f;
        r.w = (bits & (1u << (4*i+3))) ? oscale * v[i].w : 0.0f;
        if (i == 0 && lane == 0) r.x = first_val;  // out[row][0]
        __stcs(op + lane + i * 32, r);
    }
}

extern "C" void kernel_launch(void* const* d_in, const int* in_sizes, int n_in,
                              void* d_out, int out_size)
{
    const float* vecs      = (const float*)d_in[0];
    const float* curvature = (const float*)d_in[1];
    const float* mask_u    = (const float*)d_in[2];
    float* out = (float*)d_out;

    const int n_rows = in_sizes[0] / D;                 // 16384
    const int blocks = n_rows / ROWS_PER_BLOCK;         // 2048
    dropout_hyperbolic_kernel<<<blocks, THREADS>>>(vecs, curvature, mask_u, out);
}

// round 15
// speedup vs baseline: 1.0170x; 1.0170x over previous
#include <cuda_runtime.h>
#include <math.h>

#define D 512
#define ROWS_PER_BLOCK 16      // 8 warps x 2 rows per warp
#define THREADS 256
#define RATE 0.1f
#define CLIP_MAG 8.0f
#define EPS 1e-4f
#define ACOSH_MIN 1.0001f

__global__ __launch_bounds__(THREADS, 4)   // 64-reg cap: room for 2 rows of v
void dropout_hyperbolic_kernel(const float* __restrict__ vecs,
                               const float* __restrict__ curvature,
                               const float* __restrict__ mask_u,
                               float* __restrict__ out)
{
    const int warp = threadIdx.x >> 5;
    const int lane = threadIdx.x & 31;
    const int rowA = blockIdx.x * ROWS_PER_BLOCK + warp * 2;
    const int rowB = rowA + 1;

    const float4* vpA = reinterpret_cast<const float4*>(vecs   + rowA * D);
    const float4* mpA = reinterpret_cast<const float4*>(mask_u + rowA * D);
    const float4* vpB = reinterpret_cast<const float4*>(vecs   + rowB * D);
    const float4* mpB = reinterpret_cast<const float4*>(mask_u + rowB * D);
    float4*       opA = reinterpret_cast<float4*>(out + rowA * D);
    float4*       opB = reinterpret_cast<float4*>(out + rowB * D);

    // Row A loads first (v then mask), then row B: ptxas interleaves the
    // mask folds between load groups to stay under the 64-reg cap while
    // keeping ~12 LDG.128 in flight.
    float4 vA[4], mA[4], vB[4], mB[4];
    #pragma unroll
    for (int i = 0; i < 4; i++) vA[i] = vpA[lane + i * 32];
    #pragma unroll
    for (int i = 0; i < 4; i++) mA[i] = mpA[lane + i * 32];
    #pragma unroll
    for (int i = 0; i < 4; i++) vB[i] = vpB[lane + i * 32];
    #pragma unroll
    for (int i = 0; i < 4; i++) mB[i] = mpB[lane + i * 32];

    // Element 0 of each row is the hyperboloid coordinate: excluded from
    // sums; its output is overwritten below.
    if (lane == 0) { vA[0].x = 0.0f; vB[0].x = 0.0f; }

    // Fold masks into bitmasks + sums (frees all mask registers).
    unsigned bitsA = 0u, bitsB = 0u;
    float sA = 0.0f, skA = 0.0f, sB = 0.0f, skB = 0.0f;
    #pragma unroll
    for (int i = 0; i < 4; i++) {
        bool a0 = (mA[i].x >= RATE), a1 = (mA[i].y >= RATE);
        bool a2 = (mA[i].z >= RATE), a3 = (mA[i].w >= RATE);
        bitsA |= (unsigned(a0) << (4*i)) | (unsigned(a1) << (4*i+1))
               | (unsigned(a2) << (4*i+2)) | (unsigned(a3) << (4*i+3));
        float x0 = vA[i].x * vA[i].x, x1 = vA[i].y * vA[i].y;
        float x2 = vA[i].z * vA[i].z, x3 = vA[i].w * vA[i].w;
        sA += x0 + x1 + x2 + x3;
        skA += (a0 ? x0 : 0.0f) + (a1 ? x1 : 0.0f)
             + (a2 ? x2 : 0.0f) + (a3 ? x3 : 0.0f);
    }
    #pragma unroll
    for (int i = 0; i < 4; i++) {
        bool b0 = (mB[i].x >= RATE), b1 = (mB[i].y >= RATE);
        bool b2 = (mB[i].z >= RATE), b3 = (mB[i].w >= RATE);
        bitsB |= (unsigned(b0) << (4*i)) | (unsigned(b1) << (4*i+1))
               | (unsigned(b2) << (4*i+2)) | (unsigned(b3) << (4*i+3));
        float x0 = vB[i].x * vB[i].x, x1 = vB[i].y * vB[i].y;
        float x2 = vB[i].z * vB[i].z, x3 = vB[i].w * vB[i].w;
        sB += x0 + x1 + x2 + x3;
        skB += (b0 ? x0 : 0.0f) + (b1 ? x1 : 0.0f)
             + (b2 ? x2 : 0.0f) + (b3 ? x3 : 0.0f);
    }

    // Butterfly reduce: 4 independent values interleave in the SHFL pipe.
    #pragma unroll
    for (int off = 16; off > 0; off >>= 1) {
        sA  += __shfl_xor_sync(0xFFFFFFFFu, sA,  off);
        skA += __shfl_xor_sync(0xFFFFFFFFu, skA, off);
        sB  += __shfl_xor_sync(0xFFFFFFFFu, sB,  off);
        skB += __shfl_xor_sync(0xFFFFFFFFu, skB, off);
    }

    // Two independent scalar tails — MUFU/FMA chains interleave (ILP-2).
    const float c = __ldg(curvature);
    const float sqrt_c = sqrtf(c);
    const float inv_keep = 1.0f / (1.0f - RATE);

    float argA = fmaxf(sqrtf(c + sA) / sqrt_c - EPS, ACOSH_MIN);
    float argB = fmaxf(sqrtf(c + sB) / sqrt_c - EPS, ACOSH_MIN);
    float distA = sqrt_c * __logf(argA + sqrtf(fmaf(argA, argA, -1.0f)));
    float distB = sqrt_c * __logf(argB + sqrtf(fmaf(argB, argB, -1.0f)));
    float sc1A = distA / (sqrtf(sA) + EPS);
    float sc1B = distB / (sqrtf(sB) + EPS);

    float tA = sc1A * sc1A * skA * (inv_keep * inv_keep);
    float tB = sc1B * sc1B * skB * (inv_keep * inv_keep);
    float snvA = sqrtf(tA) / sqrt_c + EPS;
    float snvB = sqrtf(tB) / sqrt_c + EPS;
    float snvcA = fminf(fmaxf(snvA, -CLIP_MAG), CLIP_MAG);
    float snvcB = fminf(fmaxf(snvB, -CLIP_MAG), CLIP_MAG);

    float eA = __expf(snvcA), eiA = 1.0f / eA;
    float eB = __expf(snvcB), eiB = 1.0f / eB;

    const float oscaleA = (0.5f * (eA - eiA) / snvA) * sc1A * inv_keep;
    const float oscaleB = (0.5f * (eB - eiB) / snvB) * sc1B * inv_keep;
    const float firstA  = 0.5f * (eA + eiA) * sqrt_c;
    const float firstB  = 0.5f * (eB + eiB) * sqrt_c;

    // Streaming stores (evict-first): output is never read.
    #pragma unroll
    for (int i = 0; i < 4; i++) {
        float4 r;
        r.x = (bitsA & (1u << (4*i)))   ? oscaleA * vA[i].x : 0.0f;
        r.y = (bitsA & (1u << (4*i+1))) ? oscaleA * vA[i].y : 0.0f;
        r.z = (bitsA & (1u << (4*i+2))) ? oscaleA * vA[i].z : 0.0f;
        r.w = (bitsA & (1u << (4*i+3))) ? oscaleA * vA[i].w : 0.0f;
        if (i == 0 && lane == 0) r.x = firstA;
        __stcs(opA + lane + i * 32, r);
    }
    #pragma unroll
    for (int i = 0; i < 4; i++) {
        float4 r;
        r.x = (bitsB & (1u << (4*i)))   ? oscaleB * vB[i].x : 0.0f;
        r.y = (bitsB & (1u << (4*i+1))) ? oscaleB * vB[i].y : 0.0f;
        r.z = (bitsB & (1u << (4*i+2))) ? oscaleB * vB[i].z : 0.0f;
        r.w = (bitsB & (1u << (4*i+3))) ? oscaleB * vB[i].w : 0.0f;
        if (i == 0 && lane == 0) r.x = firstB;
        __stcs(opB + lane + i * 32, r);
    }
}

extern "C" void kernel_launch(void* const* d_in, const int* in_sizes, int n_in,
                              void* d_out, int out_size)
{
    const float* vecs      = (const float*)d_in[0];
    const float* curvature = (const float*)d_in[1];
    const float* mask_u    = (const float*)d_in[2];
    float* out = (float*)d_out;

    const int n_rows = in_sizes[0] / D;                 // 16384
    const int blocks = n_rows / ROWS_PER_BLOCK;         // 1024
    dropout_hyperbolic_kernel<<<blocks, THREADS>>>(vecs, curvature, mask_u, out);
}

// round 16
// speedup vs baseline: 1.1405x; 1.1214x over previous
#include <cuda_runtime.h>
#include <math.h>

#define D 512
#define ROWS_PER_BLOCK 8
#define THREADS 256            // 8 warps, 1 row per warp, 16 elems/lane
#define RATE 0.1f
#define CLIP_MAG 8.0f
#define EPS 1e-4f
#define ACOSH_MIN 1.0001f

// Final configuration (validated over R5/R10/R12/R14):
//  - warp-per-row, zero barriers; butterfly SHFL reduce
//  - 8 front-batched LDG.128 per thread; scalar curvature load AFTER them
//    (R9: same-line scalar load first pollutes the L1tex wavefront queue)
//  - keep-mask packed to 16 bits (regs=32, full residency headroom)
//  - MUFU-based acosh/cosh/sinh, computed redundantly lane-wide (warp-issue)
//  - __stcs evict-first stores: output never evicts L2-resident inputs
//    between graph replays (R5: warm −2us, cold unchanged)
// Closed branches: 256-bit evict_last loads (R7/R8), scalar hoist (R9),
// redux.f32 (not in sm_103 ISA, R11), persistent grid (R13), ILP-2 (R15).

__global__ __launch_bounds__(THREADS, 8)
void dropout_hyperbolic_kernel(const float* __restrict__ vecs,
                               const float* __restrict__ curvature,
                               const float* __restrict__ mask_u,
                               float* __restrict__ out)
{
    const int warp = threadIdx.x >> 5;
    const int lane = threadIdx.x & 31;
    const int row  = blockIdx.x * ROWS_PER_BLOCK + warp;

    const float4* vp = reinterpret_cast<const float4*>(vecs  + row * D);
    const float4* mp = reinterpret_cast<const float4*>(mask_u + row * D);
    float4*       op = reinterpret_cast<float4*>(out + row * D);

    // Front-batched, fully-coalesced loads: chunk i covers elements
    // [i*128 + lane*4, +4). 8 LDG.128 in flight per thread.
    float4 v[4], m[4];
    #pragma unroll
    for (int i = 0; i < 4; i++) v[i] = vp[lane + i * 32];
    #pragma unroll
    for (int i = 0; i < 4; i++) m[i] = mp[lane + i * 32];

    // Row element 0 (lane 0, chunk 0, .x) is the hyperboloid coordinate:
    // excluded from both sums; its output is overwritten below anyway.
    if (lane == 0) v[0].x = 0.0f;

    // Pack keep decisions into a 16-bit mask (bit 4*i+j for chunk i comp j)
    // and accumulate s = sum v^2, sk = sum v^2*keep in the same pass.
    unsigned bits = 0u;
    float s_loc = 0.0f, sk_loc = 0.0f;
    #pragma unroll
    for (int i = 0; i < 4; i++) {
        bool b0 = (m[i].x >= RATE);
        bool b1 = (m[i].y >= RATE);
        bool b2 = (m[i].z >= RATE);
        bool b3 = (m[i].w >= RATE);
        bits |= (unsigned(b0) << (4*i)) | (unsigned(b1) << (4*i+1))
              | (unsigned(b2) << (4*i+2)) | (unsigned(b3) << (4*i+3));
        float x0 = v[i].x * v[i].x;
        float x1 = v[i].y * v[i].y;
        float x2 = v[i].z * v[i].z;
        float x3 = v[i].w * v[i].w;
        s_loc += x0 + x1 + x2 + x3;
        sk_loc += (b0 ? x0 : 0.0f) + (b1 ? x1 : 0.0f)
                + (b2 ? x2 : 0.0f) + (b3 ? x3 : 0.0f);
    }

    // Butterfly reduce — all lanes end with the row totals. No barriers.
    #pragma unroll
    for (int off = 16; off > 0; off >>= 1) {
        s_loc  += __shfl_xor_sync(0xFFFFFFFFu, s_loc,  off);
        sk_loc += __shfl_xor_sync(0xFFFFFFFFu, sk_loc, off);
    }

    // Per-row scalar tail, computed redundantly by all 32 lanes (warp-wide
    // issue: same cost as 1 lane, no broadcast needed).
    const float c = __ldg(curvature);
    const float sqrt_c = sqrtf(c);
    const float inv_keep = 1.0f / (1.0f - RATE);

    float arg = sqrtf(c + s_loc) / sqrt_c - EPS;
    arg = fmaxf(arg, ACOSH_MIN);
    // acosh(x) = log(x + sqrt(x^2 - 1)); arg >= 1.0001 so stable.
    float dist = sqrt_c * __logf(arg + sqrtf(fmaf(arg, arg, -1.0f)));
    float scale1 = dist / (sqrtf(s_loc) + EPS);

    float t = scale1 * scale1 * sk_loc * (inv_keep * inv_keep);
    float snv = sqrtf(t) / sqrt_c + EPS;
    float snv_c = fminf(fmaxf(snv, -CLIP_MAG), CLIP_MAG);

    float e  = __expf(snv_c);
    float ei = 1.0f / e;
    float cosh_v = 0.5f * (e + ei);
    float sinh_v = 0.5f * (e - ei);

    const float oscale    = (sinh_v / snv) * scale1 * inv_keep;
    const float first_val = cosh_v * sqrt_c;

    // Output pass: reconstruct dropped values from the bitmask.
    // Streaming stores (evict-first): the output is never read, so keep it
    // from evicting the L2-resident inputs between graph replays.
    #pragma unroll
    for (int i = 0; i < 4; i++) {
        float4 r;
        r.x = (bits & (1u << (4*i)))   ? oscale * v[i].x : 0.0f;
        r.y = (bits & (1u << (4*i+1))) ? oscale * v[i].y : 0.0f;
        r.z = (bits & (1u << (4*i+2))) ? oscale * v[i].z : 0.0f;
        r.w = (bits & (1u << (4*i+3))) ? oscale * v[i].w : 0.0f;
        if (i == 0 && lane == 0) r.x = first_val;  // out[row][0]
        __stcs(op + lane + i * 32, r);
    }
}

extern "C" void kernel_launch(void* const* d_in, const int* in_sizes, int n_in,
                              void* d_out, int out_size)
{
    const float* vecs      = (const float*)d_in[0];
    const float* curvature = (const float*)d_in[1];
    const float* mask_u    = (const float*)d_in[2];
    float* out = (float*)d_out;

    const int n_rows = in_sizes[0] / D;                 // 16384
    const int blocks = n_rows / ROWS_PER_BLOCK;         // 2048
    dropout_hyperbolic_kernel<<<blocks, THREADS>>>(vecs, curvature, mask_u, out);
}

// round 17
// speedup vs baseline: 1.1711x; 1.0269x over previous
#include <cuda_runtime.h>
#include <math.h>

#define D 512
#define ROWS_PER_BLOCK 8
#define THREADS 256            // 8 warps, 1 row per warp, 16 elems/lane
#define RATE 0.1f
#define CLIP_MAG 8.0f
#define EPS 1e-4f
#define ACOSH_MIN 1.0001f

// Final configuration (validated over R5/R10/R12/R14/R16; best 13.09us,
// band 13.1-15.3us run-to-run on byte-identical source):
//  - warp-per-row, zero barriers; butterfly SHFL reduce
//  - 8 front-batched LDG.128 per thread; scalar curvature load AFTER them
//    (R9: same-line scalar load first pollutes the L1tex wavefront queue)
//  - keep-mask packed to 16 bits (regs=32, full residency headroom)
//  - MUFU-based acosh/cosh/sinh, computed redundantly lane-wide (warp-issue)
//  - __stcs evict-first stores: output never evicts L2-resident inputs
//    between graph replays (R5: warm −2us, cold unchanged)
// Closed branches: 256-bit evict_last loads (R7/R8), scalar hoist (R9),
// redux.f32 (not in sm_103 ISA, R11), persistent grid (R13), ILP-2 (R15),
// occupancy tuning (R4). Kernel is at the LTS/mixed-traffic ceiling.

__global__ __launch_bounds__(THREADS, 8)
void dropout_hyperbolic_kernel(const float* __restrict__ vecs,
                               const float* __restrict__ curvature,
                               const float* __restrict__ mask_u,
                               float* __restrict__ out)
{
    const int warp = threadIdx.x >> 5;
    const int lane = threadIdx.x & 31;
    const int row  = blockIdx.x * ROWS_PER_BLOCK + warp;

    const float4* vp = reinterpret_cast<const float4*>(vecs  + row * D);
    const float4* mp = reinterpret_cast<const float4*>(mask_u + row * D);
    float4*       op = reinterpret_cast<float4*>(out + row * D);

    // Front-batched, fully-coalesced loads: chunk i covers elements
    // [i*128 + lane*4, +4). 8 LDG.128 in flight per thread.
    float4 v[4], m[4];
    #pragma unroll
    for (int i = 0; i < 4; i++) v[i] = vp[lane + i * 32];
    #pragma unroll
    for (int i = 0; i < 4; i++) m[i] = mp[lane + i * 32];

    // Row element 0 (lane 0, chunk 0, .x) is the hyperboloid coordinate:
    // excluded from both sums; its output is overwritten below anyway.
    if (lane == 0) v[0].x = 0.0f;

    // Pack keep decisions into a 16-bit mask (bit 4*i+j for chunk i comp j)
    // and accumulate s = sum v^2, sk = sum v^2*keep in the same pass.
    unsigned bits = 0u;
    float s_loc = 0.0f, sk_loc = 0.0f;
    #pragma unroll
    for (int i = 0; i < 4; i++) {
        bool b0 = (m[i].x >= RATE);
        bool b1 = (m[i].y >= RATE);
        bool b2 = (m[i].z >= RATE);
        bool b3 = (m[i].w >= RATE);
        bits |= (unsigned(b0) << (4*i)) | (unsigned(b1) << (4*i+1))
              | (unsigned(b2) << (4*i+2)) | (unsigned(b3) << (4*i+3));
        float x0 = v[i].x * v[i].x;
        float x1 = v[i].y * v[i].y;
        float x2 = v[i].z * v[i].z;
        float x3 = v[i].w * v[i].w;
        s_loc += x0 + x1 + x2 + x3;
        sk_loc += (b0 ? x0 : 0.0f) + (b1 ? x1 : 0.0f)
                + (b2 ? x2 : 0.0f) + (b3 ? x3 : 0.0f);
    }

    // Butterfly reduce — all lanes end with the row totals. No barriers.
    #pragma unroll
    for (int off = 16; off > 0; off >>= 1) {
        s_loc  += __shfl_xor_sync(0xFFFFFFFFu, s_loc,  off);
        sk_loc += __shfl_xor_sync(0xFFFFFFFFu, sk_loc, off);
    }

    // Per-row scalar tail, computed redundantly by all 32 lanes (warp-wide
    // issue: same cost as 1 lane, no broadcast needed).
    const float c = __ldg(curvature);
    const float sqrt_c = sqrtf(c);
    const float inv_keep = 1.0f / (1.0f - RATE);

    float arg = sqrtf(c + s_loc) / sqrt_c - EPS;
    arg = fmaxf(arg, ACOSH_MIN);
    // acosh(x) = log(x + sqrt(x^2 - 1)); arg >= 1.0001 so stable.
    float dist = sqrt_c * __logf(arg + sqrtf(fmaf(arg, arg, -1.0f)));
    float scale1 = dist / (sqrtf(s_loc) + EPS);

    float t = scale1 * scale1 * sk_loc * (inv_keep * inv_keep);
    float snv = sqrtf(t) / sqrt_c + EPS;
    float snv_c = fminf(fmaxf(snv, -CLIP_MAG), CLIP_MAG);

    float e  = __expf(snv_c);
    float ei = 1.0f / e;
    float cosh_v = 0.5f * (e + ei);
    float sinh_v = 0.5f * (e - ei);

    const float oscale    = (sinh_v / snv) * scale1 * inv_keep;
    const float first_val = cosh_v * sqrt_c;

    // Output pass: reconstruct dropped values from the bitmask.
    // Streaming stores (evict-first): the output is never read, so keep it
    // from evicting the L2-resident inputs between graph replays.
    #pragma unroll
    for (int i = 0; i < 4; i++) {
        float4 r;
        r.x = (bits & (1u << (4*i)))   ? oscale * v[i].x : 0.0f;
        r.y = (bits & (1u << (4*i+1))) ? oscale * v[i].y : 0.0f;
        r.z = (bits & (1u << (4*i+2))) ? oscale * v[i].z : 0.0f;
        r.w = (bits & (1u << (4*i+3))) ? oscale * v[i].w : 0.0f;
        if (i == 0 && lane == 0) r.x = first_val;  // out[row][0]
        __stcs(op + lane + i * 32, r);
    }
}

extern "C" void kernel_launch(void* const* d_in, const int* in_sizes, int n_in,
                              void* d_out, int out_size)
{
    const float* vecs      = (const float*)d_in[0];
    const float* curvature = (const float*)d_in[1];
    const float* mask_u    = (const float*)d_in[2];
    float* out = (float*)d_out;

    const int n_rows = in_sizes[0] / D;                 // 16384
    const int blocks = n_rows / ROWS_PER_BLOCK;         // 2048
    dropout_hyperbolic_kernel<<<blocks, THREADS>>>(vecs, curvature, mask_u, out);
}